// round 9
// baseline (speedup 1.0000x reference)
#include <cuda_runtime.h>
#include <cstdint>

#define SDIM 2048
#define EDIM 256
#define BDIM 8

__device__ float g_Q[BDIM * SDIM * EDIM];      // Q[b][s][f]
__device__ float g_poolT[BDIM * SDIM * EDIM];  // pooled^T [b][s][e], tf32-rounded
__device__ float g_Wqr[EDIM * EDIM];           // Wq tf32-rounded
__device__ float g_Wor[EDIM * EDIM];           // Wo tf32-rounded

static __device__ __forceinline__ uint32_t smem_u32(const void* p) {
    uint32_t a;
    asm("{ .reg .u64 t; cvta.to.shared.u64 t, %1; cvt.u32.u64 %0, t; }" : "=r"(a) : "l"(p));
    return a;
}
static __device__ __forceinline__ void cp4(uint32_t dst, const float* src) {
    asm volatile("cp.async.ca.shared.global [%0], [%1], 4;" :: "r"(dst), "l"(src));
}
static __device__ __forceinline__ void cp16(uint32_t dst, const float* src) {
    asm volatile("cp.async.ca.shared.global [%0], [%1], 16;" :: "r"(dst), "l"(src));
}
static __device__ __forceinline__ void cp_commit() {
    asm volatile("cp.async.commit_group;" ::: "memory");
}
template <int N>
static __device__ __forceinline__ void cp_wait() {
    asm volatile("cp.async.wait_group %0;" :: "n"(N) : "memory");
}
static __device__ __forceinline__ uint32_t rntf32(float f) {
    uint32_t u;
    asm("cvt.rn.tf32.f32 %0, %1;" : "=r"(u) : "f"(f));
    return u;
}

// mma.sync m16n8k8 tf32: D += A*B  (row.col), fp32 accum
static __device__ __forceinline__ void mma_tf32(float* d, const uint32_t* a, const uint32_t* b) {
    asm volatile(
        "mma.sync.aligned.m16n8k8.row.col.f32.tf32.tf32.f32 "
        "{%0,%1,%2,%3}, {%4,%5,%6,%7}, {%8,%9}, {%0,%1,%2,%3};"
        : "+f"(d[0]), "+f"(d[1]), "+f"(d[2]), "+f"(d[3])
        : "r"(a[0]), "r"(a[1]), "r"(a[2]), "r"(a[3]), "r"(b[0]), "r"(b[1]));
}

#define LDSM_X4(r, a)                                                     \
    asm volatile("ldmatrix.sync.aligned.m8n8.x4.shared.b16 "              \
                 "{%0,%1,%2,%3}, [%4];"                                   \
                 : "=r"((r)[0]), "=r"((r)[1]), "=r"((r)[2]), "=r"((r)[3]) \
                 : "r"(a))

// ---------------------------------------------------------------------------
// tf32 tensor-core GEMM (unchanged from R8): cp.async 3-stage, XOR-swizzled
// K-major SMEM, ldmatrix.x4 fragment loads.
// ---------------------------------------------------------------------------
template <int TRANS_A, int CVT_A, int BIAS_M>
__global__ void __launch_bounds__(256, 2)
gemm_mma(const float* __restrict__ A, int lda, long sA,
         const float* __restrict__ B, int ldb, long sB,
         float* __restrict__ C, int ldc, long sC,
         const float* __restrict__ bias, float scale) {
    extern __shared__ float smraw[];
    const uint32_t smb128 = (smem_u32(smraw) + 127) & ~127u;

    const int tid = threadIdx.x, lane = tid & 31, wid = tid >> 5;
    const int wm = wid & 3, wn = wid >> 2;
    const int bn0 = blockIdx.x * 128, bm0 = blockIdx.y * 128;
    A += sA * blockIdx.z; B += sB * blockIdx.z; C += sC * blockIdx.z;

    float d[2][8][4];
#pragma unroll
    for (int mt = 0; mt < 2; mt++)
#pragma unroll
        for (int nt = 0; nt < 8; nt++)
#pragma unroll
            for (int q = 0; q < 4; q++) d[mt][nt][q] = 0.0f;

    const int r7 = lane & 7;
    uint32_t offAb[2], offBb[4];
#pragma unroll
    for (int mt = 0; mt < 2; mt++) {
        int m = wm * 32 + mt * 16 + r7 + ((lane >> 3) & 1) * 8;
        offAb[mt] = (uint32_t)(m * 128 + (((lane >> 4) ^ r7) << 4));
    }
#pragma unroll
    for (int p = 0; p < 4; p++) {
        int n = wn * 64 + p * 16 + r7 + ((lane >> 4) & 1) * 8;
        offBb[p] = (uint32_t)(n * 128 + ((((lane >> 3) & 1) ^ r7) << 4));
    }

    auto fill = [&](int slot, int k0) {
        uint32_t aS = smb128 + slot * 32768;
        uint32_t bS = aS + 16384;
        if (TRANS_A) {
#pragma unroll
            for (int p = 0; p < 16; p++) {
                int idx = tid + p * 256;
                int m = idx & 127, kk = idx >> 7;
                cp4(aS + m * 128 + ((((kk >> 2) ^ (m & 7)) << 4)) + (kk & 3) * 4,
                    A + (long)(k0 + kk) * lda + bm0 + m);
            }
        } else {
#pragma unroll
            for (int p = 0; p < 4; p++) {
                int idx = tid + p * 256;
                int row = idx >> 3, ch = idx & 7;
                cp16(aS + row * 128 + (((ch ^ (row & 7)) << 4)),
                     A + (long)(bm0 + row) * lda + k0 + ch * 4);
            }
        }
#pragma unroll
        for (int p = 0; p < 4; p++) {
            int idx = tid + p * 256;
            int row = idx >> 3, ch = idx & 7;
            cp16(bS + row * 128 + (((ch ^ (row & 7)) << 4)),
                 B + (long)(bn0 + row) * ldb + k0 + ch * 4);
        }
    };

    auto compute = [&](int slot) {
        uint32_t aS = smb128 + slot * 32768;
        uint32_t bS = aS + 16384;
#pragma unroll
        for (int k8 = 0; k8 < 4; k8++) {
            const uint32_t kx = (uint32_t)(k8 << 5);
            uint32_t afr[2][4], bfr[4][4];
#pragma unroll
            for (int mt = 0; mt < 2; mt++) {
                LDSM_X4(afr[mt], (aS + offAb[mt]) ^ kx);
                if (CVT_A) {
#pragma unroll
                    for (int q = 0; q < 4; q++)
                        afr[mt][q] = rntf32(__uint_as_float(afr[mt][q]));
                }
            }
#pragma unroll
            for (int p = 0; p < 4; p++) LDSM_X4(bfr[p], (bS + offBb[p]) ^ kx);
#pragma unroll
            for (int mt = 0; mt < 2; mt++)
#pragma unroll
                for (int p = 0; p < 4; p++) {
                    mma_tf32(d[mt][2 * p],     afr[mt], &bfr[p][0]);
                    mma_tf32(d[mt][2 * p + 1], afr[mt], &bfr[p][2]);
                }
        }
    };

    fill(0, 0); cp_commit();
    fill(1, 32); cp_commit();

#pragma unroll 1
    for (int kt = 0; kt < 8; kt++) {
        if (kt == 7) cp_wait<0>(); else cp_wait<1>();
        __syncthreads();
        if (kt + 2 < 8) { fill((kt + 2) % 3, (kt + 2) * 32); cp_commit(); }
        compute(kt % 3);
    }

    const int mrow = bm0 + wm * 32 + (lane >> 2);
    const int ncol = bn0 + wn * 64 + (lane & 3) * 2;
#pragma unroll
    for (int mt = 0; mt < 2; mt++) {
        int m0 = mrow + mt * 16;
#pragma unroll
        for (int nt = 0; nt < 8; nt++) {
            int c = ncol + nt * 8;
            float b0, b1, b2;
            if (BIAS_M) { b0 = bias[m0]; b2 = bias[m0 + 8]; b1 = 0.0f; }
            else { b0 = bias[c]; b1 = bias[c + 1]; b2 = 0.0f; }
            float2 lo, hi;
            if (BIAS_M) {
                lo.x = (d[mt][nt][0] + b0) * scale; lo.y = (d[mt][nt][1] + b0) * scale;
                hi.x = (d[mt][nt][2] + b2) * scale; hi.y = (d[mt][nt][3] + b2) * scale;
            } else {
                lo.x = (d[mt][nt][0] + b0) * scale; lo.y = (d[mt][nt][1] + b1) * scale;
                hi.x = (d[mt][nt][2] + b0) * scale; hi.y = (d[mt][nt][3] + b1) * scale;
            }
            *(float2*)(C + (long)m0 * ldc + c) = lo;
            *(float2*)(C + (long)(m0 + 8) * ldc + c) = hi;
        }
    }
}

// ---------------------------------------------------------------------------
__global__ void round_weights(const float* __restrict__ Wq, const float* __restrict__ Wo) {
    int i = blockIdx.x * 256 + threadIdx.x;
    const float4 v = ((const float4*)(blockIdx.y ? Wo : Wq))[i];
    float4 r;
    r.x = __uint_as_float(rntf32(v.x));
    r.y = __uint_as_float(rntf32(v.y));
    r.z = __uint_as_float(rntf32(v.z));
    r.w = __uint_as_float(rntf32(v.w));
    ((float4*)(blockIdx.y ? g_Wor : g_Wqr))[i] = r;
}

// ---------------------------------------------------------------------------
// Fused attention + pooling. One CTA per (s-block of 128, batch).
// P1: QS[136][256] <- Q rows s0-4..s0+131 (OOB -> bq)
// P2a: D[t][j] = QS[t].QS[t+j], j=0..4 (symmetric dots, 5-row reg window)
// P2b: softmax row s from D[s+4][j] and D[s+4-j][j] -> a_sm[128][12]
// P3: XS[256][137] <- x window [s0-4, s0+132) (aliases QS; OOB -> 0)
// P4: poolT[s][e] = sum_l a[s][l] * XS[e][s+l], tf32-rounded, coalesced STG
// ---------------------------------------------------------------------------
__global__ void __launch_bounds__(512, 1)
attnpool_fused(const float* __restrict__ x, const float* __restrict__ bq) {
    extern __shared__ float sf[];
    float* QS = sf;                    // 136*256 = 34816 floats
    float* XS = sf;                    // 256*137 = 35072 floats (alias of QS)
    float* d_sm = sf + 35072;          // 136*8   = 1088
    float* a_sm = sf + 35072 + 1088;   // 128*12  = 1536

    const int b = blockIdx.y, s0 = blockIdx.x * 128;
    const int tid = threadIdx.x, lane = tid & 31, w = tid >> 5;
    const float* Qb = g_Q + (long)b * SDIM * EDIM;

    // ---- P1: load Q tile ----
#pragma unroll
    for (int p = 0; p < 17; p++) {
        int idx = tid + p * 512;            // 0..8703
        int r = idx >> 6, f4 = idx & 63;
        int s = s0 - 4 + r;
        float4 v = (s >= 0 && s < SDIM) ? ((const float4*)(Qb + (long)s * EDIM))[f4]
                                        : ((const float4*)bq)[f4];
        ((float4*)QS)[r * 64 + f4] = v;
    }
    __syncthreads();

    // ---- P2a: symmetric dots, each Q row read once ----
    {
        int t0 = w * 9;                      // warps 0..15 -> t0 0..135
        if (t0 < 136) {
            float R[5][8];
#pragma unroll
            for (int q = 0; q < 4; q++) {
                int rr = min(t0 + q, 135);
                *(float4*)&R[q][0] = ((float4*)QS)[rr * 64 + lane * 2];
                *(float4*)&R[q][4] = ((float4*)QS)[rr * 64 + lane * 2 + 1];
            }
#pragma unroll 1
            for (int i = 0; i < 9; i++) {
                int t = t0 + i;
                if (t >= 136) break;
                int s4 = (i + 4) % 5;
                if (t + 4 < 136) {
                    *(float4*)&R[s4][0] = ((float4*)QS)[(t + 4) * 64 + lane * 2];
                    *(float4*)&R[s4][4] = ((float4*)QS)[(t + 4) * 64 + lane * 2 + 1];
                }
                float keep = 0.0f;
#pragma unroll
                for (int j = 0; j < 5; j++) {
                    if (t + j < 136) {
                        float p = 0.0f;
#pragma unroll
                        for (int f = 0; f < 8; f++) p += R[i % 5][f] * R[(i + j) % 5][f];
#pragma unroll
                        for (int off = 16; off; off >>= 1) p += __shfl_xor_sync(0xffffffffu, p, off);
                        if (lane == j) keep = p;
                    }
                }
                if (lane < 5) d_sm[t * 8 + lane] = keep;
            }
        }
    }
    __syncthreads();

    // ---- P2b: softmax (threads 0..127) ----
    if (tid < 128) {
        const int ls = tid;
        const float inv_scale = 1.0f / 24.0f;
        float E[9];
        E[4] = d_sm[(ls + 4) * 8];
#pragma unroll
        for (int j = 1; j <= 4; j++) {
            E[4 + j] = d_sm[(ls + 4) * 8 + j];
            E[4 - j] = d_sm[(ls + 4 - j) * 8 + j];
        }
        float mx = -1e30f;
#pragma unroll
        for (int l = 0; l < 9; l++) { E[l] *= inv_scale; mx = fmaxf(mx, E[l]); }
        float sum = 0.0f;
        float ev[9];
#pragma unroll
        for (int l = 0; l < 9; l++) { ev[l] = __expf(E[l] - mx); sum += ev[l]; }
        float inv = 1.0f / sum;
#pragma unroll
        for (int l = 0; l < 9; l++) a_sm[ls * 12 + l] = ev[l] * inv;
    }

    // ---- P3: load x tile into XS (aliases QS; safe after P2a barrier) ----
    {
        int e = tid & 255, seg = tid >> 8;   // 2 segments x 20 float4 per row
        const float* xe = x + ((long)b * EDIM + e) * SDIM;
#pragma unroll 1
        for (int jj = 0; jj < 10; jj++) {
#pragma unroll
            for (int u = 0; u < 2; u++) {
                int j = seg * 20 + jj * 2 + u;
                int g = s0 - 16 + j * 4;     // 16B-aligned
                float4 v = (g >= 0 && g < SDIM) ? *(const float4*)(xe + g)
                                                : make_float4(0.f, 0.f, 0.f, 0.f);
                int ib = j * 4 - 12;
#pragma unroll
                for (int c = 0; c < 4; c++) {
                    int i = ib + c;
                    if (i >= 0 && i < 136) XS[e * 137 + i] = ((const float*)&v)[c];
                }
            }
        }
    }
    __syncthreads();

    // ---- P4: pooling, lane<->e coalesced, sliding x window ----
    {
        int e = tid & 255, shalf = tid >> 8;
        const int sb0 = shalf * 64;
        const float* Xe = XS + e * 137;
        float* outb = g_poolT + ((long)b * SDIM + s0) * EDIM + e;
#pragma unroll 1
        for (int sc = 0; sc < 8; sc++) {
            const int sb = sb0 + sc * 8;
            float xw[16];
#pragma unroll
            for (int i = 0; i < 16; i++) xw[i] = Xe[sb + i];
#pragma unroll
            for (int si = 0; si < 8; si++) {
                int s = sb + si;
                float4 a03 = *(const float4*)&a_sm[s * 12];
                float4 a47 = *(const float4*)&a_sm[s * 12 + 4];
                float a8 = a_sm[s * 12 + 8];
                float acc = a03.x * xw[si]     + a03.y * xw[si + 1] +
                            a03.z * xw[si + 2] + a03.w * xw[si + 3] +
                            a47.x * xw[si + 4] + a47.y * xw[si + 5] +
                            a47.z * xw[si + 6] + a47.w * xw[si + 7] +
                            a8    * xw[si + 8];
                outb[(long)s * EDIM] = __uint_as_float(rntf32(acc));
            }
        }
    }
}

// ---------------------------------------------------------------------------
extern "C" void kernel_launch(void* const* d_in, const int* in_sizes, int n_in,
                              void* d_out, int out_size) {
    const float* x  = (const float*)d_in[0];
    const float* Wq = (const float*)d_in[1];
    const float* bq = (const float*)d_in[2];
    const float* Wo = (const float*)d_in[3];
    const float* bo = (const float*)d_in[4];
    float* out = (float*)d_out;

    float *Qp, *pt, *wqr, *wor;
    cudaGetSymbolAddress((void**)&Qp, g_Q);
    cudaGetSymbolAddress((void**)&pt, g_poolT);
    cudaGetSymbolAddress((void**)&wqr, g_Wqr);
    cudaGetSymbolAddress((void**)&wor, g_Wor);

    const int SMEM = 3 * 32768 + 128;
    const int SMEM_F = (35072 + 1088 + 1536) * 4;  // 150784 B
    cudaFuncSetAttribute((const void*)gemm_mma<1, 1, 0>, cudaFuncAttributeMaxDynamicSharedMemorySize, SMEM);
    cudaFuncSetAttribute((const void*)gemm_mma<0, 0, 1>, cudaFuncAttributeMaxDynamicSharedMemorySize, SMEM);
    cudaFuncSetAttribute((const void*)attnpool_fused, cudaFuncAttributeMaxDynamicSharedMemorySize, SMEM_F);

    // 0) round weights to tf32 grid
    round_weights<<<dim3(64, 2), 256>>>(Wq, Wo);

    // 1) Q[b][s][f] = sum_e x[b][e][s]*Wqr[f][e] + bq[f]   (m=s, n=f, k=e)
    gemm_mma<1, 1, 0><<<dim3(2, 16, BDIM), 256, SMEM>>>(
        x, SDIM, (long)EDIM * SDIM,
        wqr, EDIM, 0L,
        Qp, EDIM, (long)SDIM * EDIM,
        bq, 1.0f);

    // 2) fused attention + pooling -> pooled^T[s][e] (tf32-rounded)
    attnpool_fused<<<dim3(SDIM / 128, BDIM), 512, SMEM_F>>>(x, bq);

    // 3) out[b][f][s] = (sum_e Wor[f][e]*pooled^T[s][e] + bo[f]) / 9   (m=f, n=s, k=e)
    gemm_mma<0, 0, 1><<<dim3(16, 2, BDIM), 256, SMEM>>>(
        wor, EDIM, 0L,
        pt, EDIM, (long)SDIM * EDIM,
        out, SDIM, (long)EDIM * SDIM,
        bo, 1.0f / 9.0f);
}

// round 10
// speedup vs baseline: 1.0311x; 1.0311x over previous
#include <cuda_runtime.h>
#include <cstdint>

#define SDIM 2048
#define EDIM 256
#define BDIM 8

__device__ float g_Q[BDIM * SDIM * EDIM];      // Q[b][s][f]
__device__ float g_poolT[BDIM * SDIM * EDIM];  // pooled^T [b][s][e], tf32-rounded
__device__ float g_Wqr[EDIM * EDIM];           // Wq tf32-rounded
__device__ float g_Wor[EDIM * EDIM];           // Wo tf32-rounded

static __device__ __forceinline__ uint32_t smem_u32(const void* p) {
    uint32_t a;
    asm("{ .reg .u64 t; cvta.to.shared.u64 t, %1; cvt.u32.u64 %0, t; }" : "=r"(a) : "l"(p));
    return a;
}
static __device__ __forceinline__ void cp4(uint32_t dst, const float* src) {
    asm volatile("cp.async.ca.shared.global [%0], [%1], 4;" :: "r"(dst), "l"(src));
}
static __device__ __forceinline__ void cp16(uint32_t dst, const float* src) {
    asm volatile("cp.async.ca.shared.global [%0], [%1], 16;" :: "r"(dst), "l"(src));
}
static __device__ __forceinline__ void cp_commit() {
    asm volatile("cp.async.commit_group;" ::: "memory");
}
template <int N>
static __device__ __forceinline__ void cp_wait() {
    asm volatile("cp.async.wait_group %0;" :: "n"(N) : "memory");
}
static __device__ __forceinline__ uint32_t rntf32(float f) {
    uint32_t u;
    asm("cvt.rn.tf32.f32 %0, %1;" : "=r"(u) : "f"(f));
    return u;
}

// mma.sync m16n8k8 tf32: D += A*B  (row.col), fp32 accum
static __device__ __forceinline__ void mma_tf32(float* d, const uint32_t* a, const uint32_t* b) {
    asm volatile(
        "mma.sync.aligned.m16n8k8.row.col.f32.tf32.tf32.f32 "
        "{%0,%1,%2,%3}, {%4,%5,%6,%7}, {%8,%9}, {%0,%1,%2,%3};"
        : "+f"(d[0]), "+f"(d[1]), "+f"(d[2]), "+f"(d[3])
        : "r"(a[0]), "r"(a[1]), "r"(a[2]), "r"(a[3]), "r"(b[0]), "r"(b[1]));
}

#define LDSM_X4(r, a)                                                     \
    asm volatile("ldmatrix.sync.aligned.m8n8.x4.shared.b16 "              \
                 "{%0,%1,%2,%3}, [%4];"                                   \
                 : "=r"((r)[0]), "=r"((r)[1]), "=r"((r)[2]), "=r"((r)[3]) \
                 : "r"(a))

// ---------------------------------------------------------------------------
// tf32 tensor-core GEMM: BM=128, BN=256, K=256 (8 chunks of 32).
// 512 threads = 16 warps (4m x 4n), warp tile 32x64. ONE CTA PER SM, one wave.
// cp.async 3-stage pipeline (48KB/stage), XOR-swizzled K-major SMEM, ldmatrix.
// Tile layout (rows x 32 floats): byte(r,k) = r*128 + (((k>>2)^(r&7))<<4) + (k&3)*4
// ---------------------------------------------------------------------------
template <int TRANS_A, int CVT_A, int BIAS_M>
__global__ void __launch_bounds__(512, 1)
gemm_mma(const float* __restrict__ A, int lda, long sA,
         const float* __restrict__ B, int ldb, long sB,
         float* __restrict__ C, int ldc, long sC,
         const float* __restrict__ bias, float scale) {
    extern __shared__ float smraw[];
    const uint32_t smb128 = (smem_u32(smraw) + 127) & ~127u;

    const int tid = threadIdx.x, lane = tid & 31, wid = tid >> 5;
    const int wm = wid & 3, wn = wid >> 2;           // 4m x 4n
    const int bn0 = blockIdx.x * 256, bm0 = blockIdx.y * 128;
    A += sA * blockIdx.z; B += sB * blockIdx.z; C += sC * blockIdx.z;

    float d[2][8][4];
#pragma unroll
    for (int mt = 0; mt < 2; mt++)
#pragma unroll
        for (int nt = 0; nt < 8; nt++)
#pragma unroll
            for (int q = 0; q < 4; q++) d[mt][nt][q] = 0.0f;

    const int r7 = lane & 7;
    uint32_t offAb[2], offBb[4];
#pragma unroll
    for (int mt = 0; mt < 2; mt++) {
        int m = wm * 32 + mt * 16 + r7 + ((lane >> 3) & 1) * 8;
        offAb[mt] = (uint32_t)(m * 128 + (((lane >> 4) ^ r7) << 4));
    }
#pragma unroll
    for (int p = 0; p < 4; p++) {
        int n = wn * 64 + p * 16 + r7 + ((lane >> 4) & 1) * 8;
        offBb[p] = (uint32_t)(n * 128 + ((((lane >> 3) & 1) ^ r7) << 4));
    }

    auto fill = [&](int slot, int k0) {
        uint32_t aS = smb128 + slot * 49152;   // A 16KB | B 32KB per stage
        uint32_t bS = aS + 16384;
        if (TRANS_A) {
#pragma unroll
            for (int p = 0; p < 8; p++) {
                int idx = tid + p * 512;
                int m = idx & 127, kk = idx >> 7;
                cp4(aS + m * 128 + ((((kk >> 2) ^ (m & 7)) << 4)) + (kk & 3) * 4,
                    A + (long)(k0 + kk) * lda + bm0 + m);
            }
        } else {
#pragma unroll
            for (int p = 0; p < 2; p++) {
                int idx = tid + p * 512;
                int row = idx >> 3, ch = idx & 7;
                cp16(aS + row * 128 + (((ch ^ (row & 7)) << 4)),
                     A + (long)(bm0 + row) * lda + k0 + ch * 4);
            }
        }
#pragma unroll
        for (int p = 0; p < 4; p++) {
            int idx = tid + p * 512;
            int row = idx >> 3, ch = idx & 7;   // row 0..255
            cp16(bS + row * 128 + (((ch ^ (row & 7)) << 4)),
                 B + (long)(bn0 + row) * ldb + k0 + ch * 4);
        }
    };

    auto compute = [&](int slot) {
        uint32_t aS = smb128 + slot * 49152;
        uint32_t bS = aS + 16384;
#pragma unroll
        for (int k8 = 0; k8 < 4; k8++) {
            const uint32_t kx = (uint32_t)(k8 << 5);
            uint32_t afr[2][4], bfr[4][4];
#pragma unroll
            for (int mt = 0; mt < 2; mt++) {
                LDSM_X4(afr[mt], (aS + offAb[mt]) ^ kx);
                if (CVT_A) {
#pragma unroll
                    for (int q = 0; q < 4; q++)
                        afr[mt][q] = rntf32(__uint_as_float(afr[mt][q]));
                }
            }
#pragma unroll
            for (int p = 0; p < 4; p++) LDSM_X4(bfr[p], (bS + offBb[p]) ^ kx);
#pragma unroll
            for (int mt = 0; mt < 2; mt++)
#pragma unroll
                for (int p = 0; p < 4; p++) {
                    mma_tf32(d[mt][2 * p],     afr[mt], &bfr[p][0]);
                    mma_tf32(d[mt][2 * p + 1], afr[mt], &bfr[p][2]);
                }
        }
    };

    fill(0, 0); cp_commit();
    fill(1, 32); cp_commit();

#pragma unroll 1
    for (int kt = 0; kt < 8; kt++) {
        if (kt == 7) cp_wait<0>(); else cp_wait<1>();
        __syncthreads();
        if (kt + 2 < 8) { fill((kt + 2) % 3, (kt + 2) * 32); cp_commit(); }
        compute(kt % 3);
    }

    const int mrow = bm0 + wm * 32 + (lane >> 2);
    const int ncol = bn0 + wn * 64 + (lane & 3) * 2;
#pragma unroll
    for (int mt = 0; mt < 2; mt++) {
        int m0 = mrow + mt * 16;
#pragma unroll
        for (int nt = 0; nt < 8; nt++) {
            int c = ncol + nt * 8;
            float b0, b1, b2;
            if (BIAS_M) { b0 = bias[m0]; b2 = bias[m0 + 8]; b1 = 0.0f; }
            else { b0 = bias[c]; b1 = bias[c + 1]; b2 = 0.0f; }
            float2 lo, hi;
            if (BIAS_M) {
                lo.x = (d[mt][nt][0] + b0) * scale; lo.y = (d[mt][nt][1] + b0) * scale;
                hi.x = (d[mt][nt][2] + b2) * scale; hi.y = (d[mt][nt][3] + b2) * scale;
            } else {
                lo.x = (d[mt][nt][0] + b0) * scale; lo.y = (d[mt][nt][1] + b1) * scale;
                hi.x = (d[mt][nt][2] + b0) * scale; hi.y = (d[mt][nt][3] + b1) * scale;
            }
            *(float2*)(C + (long)m0 * ldc + c) = lo;
            *(float2*)(C + (long)(m0 + 8) * ldc + c) = hi;
        }
    }
}

// ---------------------------------------------------------------------------
__global__ void round_weights(const float* __restrict__ Wq, const float* __restrict__ Wo) {
    int i = blockIdx.x * 256 + threadIdx.x;
    const float4 v = ((const float4*)(blockIdx.y ? Wo : Wq))[i];
    float4 r;
    r.x = __uint_as_float(rntf32(v.x));
    r.y = __uint_as_float(rntf32(v.y));
    r.z = __uint_as_float(rntf32(v.z));
    r.w = __uint_as_float(rntf32(v.w));
    ((float4*)(blockIdx.y ? g_Wor : g_Wqr))[i] = r;
}

// ---------------------------------------------------------------------------
// Fused attention + pooling (logic identical to R9; P3 rewritten: aligned
// float4 loads with uniform boundary predicate, conflict-free stride-137 STS).
// ---------------------------------------------------------------------------
__global__ void __launch_bounds__(512, 1)
attnpool_fused(const float* __restrict__ x, const float* __restrict__ bq) {
    extern __shared__ float sf[];
    float* QS = sf;                    // 136*256 = 34816 floats
    float* XS = sf;                    // 256*137 = 35072 floats (alias of QS)
    float* d_sm = sf + 35072;          // 136*8   = 1088
    float* a_sm = sf + 35072 + 1088;   // 128*12  = 1536

    const int b = blockIdx.y, s0 = blockIdx.x * 128;
    const int tid = threadIdx.x, lane = tid & 31, w = tid >> 5;
    const float* Qb = g_Q + (long)b * SDIM * EDIM;

    // ---- P1: load Q tile ----
#pragma unroll
    for (int p = 0; p < 17; p++) {
        int idx = tid + p * 512;            // 0..8703
        int r = idx >> 6, f4 = idx & 63;
        int s = s0 - 4 + r;
        float4 v = (s >= 0 && s < SDIM) ? ((const float4*)(Qb + (long)s * EDIM))[f4]
                                        : ((const float4*)bq)[f4];
        ((float4*)QS)[r * 64 + f4] = v;
    }
    __syncthreads();

    // ---- P2a: symmetric dots, each Q row read once ----
    {
        int t0 = w * 9;                      // warps 0..15 -> t0 0..135
        if (t0 < 136) {
            float R[5][8];
#pragma unroll
            for (int q = 0; q < 4; q++) {
                int rr = min(t0 + q, 135);
                *(float4*)&R[q][0] = ((float4*)QS)[rr * 64 + lane * 2];
                *(float4*)&R[q][4] = ((float4*)QS)[rr * 64 + lane * 2 + 1];
            }
#pragma unroll 1
            for (int i = 0; i < 9; i++) {
                int t = t0 + i;
                if (t >= 136) break;
                int s4 = (i + 4) % 5;
                if (t + 4 < 136) {
                    *(float4*)&R[s4][0] = ((float4*)QS)[(t + 4) * 64 + lane * 2];
                    *(float4*)&R[s4][4] = ((float4*)QS)[(t + 4) * 64 + lane * 2 + 1];
                }
                float keep = 0.0f;
#pragma unroll
                for (int j = 0; j < 5; j++) {
                    if (t + j < 136) {
                        float p = 0.0f;
#pragma unroll
                        for (int f = 0; f < 8; f++) p += R[i % 5][f] * R[(i + j) % 5][f];
#pragma unroll
                        for (int off = 16; off; off >>= 1) p += __shfl_xor_sync(0xffffffffu, p, off);
                        if (lane == j) keep = p;
                    }
                }
                if (lane < 5) d_sm[t * 8 + lane] = keep;
            }
        }
    }
    __syncthreads();

    // ---- P2b: softmax (threads 0..127) ----
    if (tid < 128) {
        const int ls = tid;
        const float inv_scale = 1.0f / 24.0f;
        float E[9];
        E[4] = d_sm[(ls + 4) * 8];
#pragma unroll
        for (int j = 1; j <= 4; j++) {
            E[4 + j] = d_sm[(ls + 4) * 8 + j];
            E[4 - j] = d_sm[(ls + 4 - j) * 8 + j];
        }
        float mx = -1e30f;
#pragma unroll
        for (int l = 0; l < 9; l++) { E[l] *= inv_scale; mx = fmaxf(mx, E[l]); }
        float sum = 0.0f;
        float ev[9];
#pragma unroll
        for (int l = 0; l < 9; l++) { ev[l] = __expf(E[l] - mx); sum += ev[l]; }
        float inv = 1.0f / sum;
#pragma unroll
        for (int l = 0; l < 9; l++) a_sm[ls * 12 + l] = ev[l] * inv;
    }

    // ---- P3: load x tile into XS (aligned float4, uniform predicates) ----
    {
        int e = tid & 255, half = tid >> 8;
        const float* xe = x + ((long)b * EDIM + e) * SDIM;
#pragma unroll
        for (int p = 0; p < 17; p++) {
            int j = half * 17 + p;           // 0..33 -> i = 0..132
            int i = j * 4;
            int g = s0 - 4 + i;              // 16B-aligned (s0 mult of 128)
            float4 v;
            if (g >= 0 && g + 3 < SDIM) {
                v = *(const float4*)(xe + g);
            } else {
                v.x = (g + 0 >= 0 && g + 0 < SDIM) ? xe[g + 0] : 0.0f;
                v.y = (g + 1 >= 0 && g + 1 < SDIM) ? xe[g + 1] : 0.0f;
                v.z = (g + 2 >= 0 && g + 2 < SDIM) ? xe[g + 2] : 0.0f;
                v.w = (g + 3 >= 0 && g + 3 < SDIM) ? xe[g + 3] : 0.0f;
            }
            float* dst = XS + e * 137 + i;   // stride 137: conflict-free STS
            dst[0] = v.x; dst[1] = v.y; dst[2] = v.z; dst[3] = v.w;
        }
    }
    __syncthreads();

    // ---- P4: pooling, lane<->e coalesced, sliding x window ----
    {
        int e = tid & 255, shalf = tid >> 8;
        const int sb0 = shalf * 64;
        const float* Xe = XS + e * 137;
        float* outb = g_poolT + ((long)b * SDIM + s0) * EDIM + e;
#pragma unroll 1
        for (int sc = 0; sc < 8; sc++) {
            const int sb = sb0 + sc * 8;
            float xw[16];
#pragma unroll
            for (int i = 0; i < 16; i++) xw[i] = Xe[sb + i];
#pragma unroll
            for (int si = 0; si < 8; si++) {
                int s = sb + si;
                float4 a03 = *(const float4*)&a_sm[s * 12];
                float4 a47 = *(const float4*)&a_sm[s * 12 + 4];
                float a8 = a_sm[s * 12 + 8];
                float acc = a03.x * xw[si]     + a03.y * xw[si + 1] +
                            a03.z * xw[si + 2] + a03.w * xw[si + 3] +
                            a47.x * xw[si + 4] + a47.y * xw[si + 5] +
                            a47.z * xw[si + 6] + a47.w * xw[si + 7] +
                            a8    * xw[si + 8];
                outb[(long)s * EDIM] = __uint_as_float(rntf32(acc));
            }
        }
    }
}

// ---------------------------------------------------------------------------
extern "C" void kernel_launch(void* const* d_in, const int* in_sizes, int n_in,
                              void* d_out, int out_size) {
    const float* x  = (const float*)d_in[0];
    const float* Wq = (const float*)d_in[1];
    const float* bq = (const float*)d_in[2];
    const float* Wo = (const float*)d_in[3];
    const float* bo = (const float*)d_in[4];
    float* out = (float*)d_out;

    float *Qp, *pt, *wqr, *wor;
    cudaGetSymbolAddress((void**)&Qp, g_Q);
    cudaGetSymbolAddress((void**)&pt, g_poolT);
    cudaGetSymbolAddress((void**)&wqr, g_Wqr);
    cudaGetSymbolAddress((void**)&wor, g_Wor);

    const int SMEM_G = 3 * 49152 + 128;            // 147584 B
    const int SMEM_F = (35072 + 1088 + 1536) * 4;  // 150784 B
    cudaFuncSetAttribute((const void*)gemm_mma<1, 1, 0>, cudaFuncAttributeMaxDynamicSharedMemorySize, SMEM_G);
    cudaFuncSetAttribute((const void*)gemm_mma<0, 0, 1>, cudaFuncAttributeMaxDynamicSharedMemorySize, SMEM_G);
    cudaFuncSetAttribute((const void*)attnpool_fused, cudaFuncAttributeMaxDynamicSharedMemorySize, SMEM_F);

    // 0) round weights to tf32 grid
    round_weights<<<dim3(64, 2), 256>>>(Wq, Wo);

    // 1) Q[b][s][f] = sum_e x[b][e][s]*Wqr[f][e] + bq[f]   (m=s, n=f, k=e)
    //    BN=256 covers all of f; one wave of 128 CTAs.
    gemm_mma<1, 1, 0><<<dim3(1, 16, BDIM), 512, SMEM_G>>>(
        x, SDIM, (long)EDIM * SDIM,
        wqr, EDIM, 0L,
        Qp, EDIM, (long)SDIM * EDIM,
        bq, 1.0f);

    // 2) fused attention + pooling -> pooled^T[s][e] (tf32-rounded)
    attnpool_fused<<<dim3(SDIM / 128, BDIM), 512, SMEM_F>>>(x, bq);

    // 3) out[b][f][s] = (sum_e Wor[f][e]*pooled^T[s][e] + bo[f]) / 9   (m=f, n=s, k=e)
    gemm_mma<0, 0, 1><<<dim3(8, 2, BDIM), 512, SMEM_G>>>(
        wor, EDIM, 0L,
        pt, EDIM, (long)SDIM * EDIM,
        out, SDIM, (long)EDIM * SDIM,
        bo, 1.0f / 9.0f);
}